// round 5
// baseline (speedup 1.0000x reference)
#include <cuda_runtime.h>
#include <math.h>

#define NMAX   8192
#define NCMAX  4096          // max total cells (16^3)
#define NBLK   96
#define NTHR   256
#define NWTOT  (NBLK * NTHR / 32)   // 768 warps total
#define CUTOFF  1.5f
#define CUTOFF2 (CUTOFF * CUTOFF)

// Deterministic scratch (no device-side allocation allowed).
__device__ int      g_cid[NMAX];
__device__ float4   g_pfrac[NMAX];    // wrapped frac coords + species bits
__device__ int      g_count[NCMAX];
__device__ int      g_cursor[NCMAX];
__device__ int      g_slot[NMAX];     // sorted slot -> original atom index
__device__ float4   g_psort[NMAX];    // frac coords + species, cell-sorted
__device__ float    g_ewarp[NWTOT];   // per-warp energy partials
__device__ unsigned g_arrive;         // monotonic barrier ticket counter

// Software grid barrier. Safe because NBLK (96) <= 148 SMs => all blocks
// co-resident in wave 1. Monotonic counter: stays a multiple of NBLK across
// launches/graph replays, so no reset is needed.
__device__ __forceinline__ void grid_bar()
{
    __syncthreads();
    __threadfence();
    if (threadIdx.x == 0) {
        unsigned ticket = atomicAdd(&g_arrive, 1u);
        unsigned target = (ticket / NBLK + 1u) * NBLK;
        while (atomicAdd(&g_arrive, 0u) < target) { __nanosleep(32); }
    }
    __syncthreads();
}

__global__ __launch_bounds__(NTHR)
void fused_kernel(const float* __restrict__ pos,
                  const float* __restrict__ cell,
                  const float* __restrict__ sigm,
                  const float* __restrict__ epsm,
                  const float* __restrict__ alpm,
                  const int*   __restrict__ species,
                  float* __restrict__ out, int n)
{
    __shared__ float s_inv[9], s_cm[9];
    __shared__ int   s_dims[4];                 // ncx, ncy, ncz, ncell
    __shared__ float s_sig[64], s_eps[64], s_alp[64];
    __shared__ int   s_off[NCMAX + 1];          // per-block copy of cell offsets
    __shared__ int   s_scan[NTHR];
    __shared__ float s_red[NTHR];

    const int tid     = threadIdx.x;
    const int gid     = blockIdx.x * NTHR + tid;
    const int gstride = NBLK * NTHR;

    // ---------------- P0: zero counters, geometry, species tables ----------
    for (int c = gid; c < NCMAX; c += gstride) { g_count[c] = 0; g_cursor[c] = 0; }
    if (tid < 64) {
        s_sig[tid] = sigm[tid];
        s_eps[tid] = epsm[tid];
        s_alp[tid] = alpm[tid];
    }
    if (tid == 0) {
        float c00=cell[0], c01=cell[1], c02=cell[2];
        float c10=cell[3], c11=cell[4], c12=cell[5];
        float c20=cell[6], c21=cell[7], c22=cell[8];
        float cof00 =  (c11*c22 - c12*c21);
        float cof01 = -(c10*c22 - c12*c20);
        float cof02 =  (c10*c21 - c11*c20);
        float cof10 = -(c01*c22 - c02*c21);
        float cof11 =  (c00*c22 - c02*c20);
        float cof12 = -(c00*c21 - c01*c20);
        float cof20 =  (c01*c12 - c02*c11);
        float cof21 = -(c00*c12 - c02*c10);
        float cof22 =  (c00*c11 - c01*c10);
        float det = c00*cof00 + c01*cof01 + c02*cof02;
        float id  = 1.0f / det;
        s_inv[0]=cof00*id; s_inv[1]=cof10*id; s_inv[2]=cof20*id;
        s_inv[3]=cof01*id; s_inv[4]=cof11*id; s_inv[5]=cof21*id;
        s_inv[6]=cof02*id; s_inv[7]=cof12*id; s_inv[8]=cof22*id;
        s_cm[0]=c00; s_cm[1]=c01; s_cm[2]=c02;
        s_cm[3]=c10; s_cm[4]=c11; s_cm[5]=c12;
        s_cm[6]=c20; s_cm[7]=c21; s_cm[8]=c22;
        float lx = sqrtf(c00*c00 + c01*c01 + c02*c02);
        float ly = sqrtf(c10*c10 + c11*c11 + c12*c12);
        float lz = sqrtf(c20*c20 + c21*c21 + c22*c22);
        int ncx = max(1, min(16, (int)floorf(lx / CUTOFF)));
        int ncy = max(1, min(16, (int)floorf(ly / CUTOFF)));
        int ncz = max(1, min(16, (int)floorf(lz / CUTOFF)));
        s_dims[0] = ncx; s_dims[1] = ncy; s_dims[2] = ncz;
        s_dims[3] = ncx * ncy * ncz;
    }
    grid_bar();

    // ---------------- P1: bin atoms into cells -----------------------------
    {
        const int ncx = s_dims[0], ncy = s_dims[1], ncz = s_dims[2];
        for (int i = gid; i < n; i += gstride) {
            float px = pos[3*i], py = pos[3*i+1], pz = pos[3*i+2];
            float fx = px*s_inv[0] + py*s_inv[3] + pz*s_inv[6];
            float fy = px*s_inv[1] + py*s_inv[4] + pz*s_inv[7];
            float fz = px*s_inv[2] + py*s_inv[5] + pz*s_inv[8];
            fx -= floorf(fx); if (fx >= 1.0f) fx = 0.0f;
            fy -= floorf(fy); if (fy >= 1.0f) fy = 0.0f;
            fz -= floorf(fz); if (fz >= 1.0f) fz = 0.0f;
            int cx = min(ncx-1, (int)(fx * (float)ncx));
            int cy = min(ncy-1, (int)(fy * (float)ncy));
            int cz = min(ncz-1, (int)(fz * (float)ncz));
            int cid = (cz * ncy + cy) * ncx + cx;
            g_cid[i]   = cid;
            g_pfrac[i] = make_float4(fx, fy, fz, __int_as_float(species[i]));
            atomicAdd(&g_count[cid], 1);
        }
    }
    grid_bar();

    // ---------------- P2: per-block redundant scan + scatter ---------------
    {
        const int CH = NCMAX / NTHR;          // 16 cells per thread
        int vals[CH];
        int base = tid * CH, sum = 0;
        #pragma unroll
        for (int k = 0; k < CH; k++) { vals[k] = __ldcg(&g_count[base + k]); sum += vals[k]; }
        s_scan[tid] = sum;
        __syncthreads();
        for (int off = 1; off < NTHR; off <<= 1) {
            int add = (tid >= off) ? s_scan[tid - off] : 0;
            __syncthreads();
            s_scan[tid] += add;
            __syncthreads();
        }
        int excl = s_scan[tid] - sum;
        #pragma unroll
        for (int k = 0; k < CH; k++) { s_off[base + k] = excl; excl += vals[k]; }
        if (tid == NTHR - 1) s_off[NCMAX] = s_scan[tid];
        __syncthreads();

        for (int i = gid; i < n; i += gstride) {
            int cid  = g_cid[i];               // written by this thread in P1? (strided same) safe via L2 anyway
            int slot = s_off[cid] + atomicAdd(&g_cursor[cid], 1);
            g_slot[slot] = i;
        }
    }
    grid_bar();

    // ---------------- P3: per-cell index sort + gather ---------------------
    {
        const int ncell = s_dims[3];
        for (int c = gid; c < ncell; c += gstride) {
            int s0 = s_off[c], s1 = s_off[c + 1];
            int cnt = s1 - s0;
            if (cnt > 32) cnt = 32;
            int tmp[32];
            for (int k = 0; k < cnt; k++) tmp[k] = __ldcg(&g_slot[s0 + k]);
            for (int a = 1; a < cnt; a++) {          // insertion sort (cells ~3 atoms)
                int key = tmp[a];
                int b = a - 1;
                while (b >= 0 && tmp[b] > key) { tmp[b+1] = tmp[b]; b--; }
                tmp[b+1] = key;
            }
            for (int k = 0; k < cnt; k++) {
                g_slot[s0 + k]  = tmp[k];
                g_psort[s0 + k] = __ldcg(&g_pfrac[tmp[k]]);
            }
        }
    }
    grid_bar();

    // ---------------- P4: pair interactions (warp per atom) ----------------
    {
        const float cm0 = s_cm[0], cm1 = s_cm[1], cm2 = s_cm[2];
        const float cm3 = s_cm[3], cm4 = s_cm[4], cm5 = s_cm[5];
        const float cm6 = s_cm[6], cm7 = s_cm[7], cm8 = s_cm[8];
        const int ncx = s_dims[0], ncy = s_dims[1], ncz = s_dims[2];

        const int wid  = gid >> 5;
        const int lane = tid & 31;
        float en_acc = 0.f;

        for (int w = wid; w < n; w += NWTOT) {
            float4 me = __ldcg(&g_psort[w]);
            int myspec8 = __float_as_int(me.w) * 8;
            int cx = min(ncx-1, (int)(me.x * (float)ncx));
            int cy = min(ncy-1, (int)(me.y * (float)ncy));
            int cz = min(ncz-1, (int)(me.z * (float)ncz));

            int ncid = -1;
            if (lane < 27) {
                int ax = cx + (lane % 3) - 1;
                int ay = cy + ((lane / 3) % 3) - 1;
                int az = cz + (lane / 9) - 1;
                ax += (ax < 0) ? ncx : 0;  ax -= (ax >= ncx) ? ncx : 0;
                ay += (ay < 0) ? ncy : 0;  ay -= (ay >= ncy) ? ncy : 0;
                az += (az < 0) ? ncz : 0;  az -= (az >= ncz) ? ncz : 0;
                ncid = (az * ncy + ay) * ncx + ax;
            }
            unsigned grp = __match_any_sync(0xFFFFFFFFu, ncid);
            bool keep = (lane < 27) && ((__ffs(grp) - 1) == lane);

            int start = 0, end = 0;
            if (keep) { start = s_off[ncid]; end = s_off[ncid + 1]; }

            float fxa = 0.f, fya = 0.f, fza = 0.f, en = 0.f;
            for (int t = start; t < end; t++) {
                if (t == w) continue;                 // self
                float4 o = __ldcg(&g_psort[t]);
                float d0 = o.x - me.x; d0 -= rintf(d0);
                float d1 = o.y - me.y; d1 -= rintf(d1);
                float d2 = o.z - me.z; d2 -= rintf(d2);
                float dx = d0*cm0 + d1*cm3 + d2*cm6;
                float dy = d0*cm1 + d1*cm4 + d2*cm7;
                float dz = d0*cm2 + d1*cm5 + d2*cm8;
                float r2 = dx*dx + dy*dy + dz*dz;
                if (r2 < CUTOFF2) {
                    float r   = sqrtf(r2);
                    int   idx = myspec8 + __float_as_int(o.w);
                    float sg  = s_sig[idx];
                    float fc  = 1.0f - r / sg;
                    if (fc > 0.0f) {
                        float ep  = s_eps[idx];
                        float al  = s_alp[idx];
                        float fa1 = powf(fc, al - 1.0f);     // f^(alpha-1)
                        en += (ep / al) * fa1 * fc;          // (eps/alpha) f^alpha
                        float coef = -(ep / sg) * fa1 / r;   // e'(r)/r
                        fxa += coef * dx;
                        fya += coef * dy;
                        fza += coef * dz;
                    }
                }
            }

            __syncwarp();
            #pragma unroll
            for (int off = 16; off; off >>= 1) {     // deterministic fixed-order tree
                fxa += __shfl_xor_sync(0xFFFFFFFFu, fxa, off);
                fya += __shfl_xor_sync(0xFFFFFFFFu, fya, off);
                fza += __shfl_xor_sync(0xFFFFFFFFu, fza, off);
                en  += __shfl_xor_sync(0xFFFFFFFFu, en,  off);
            }
            if (lane == 0) {
                int orig = __ldcg(&g_slot[w]);
                out[1 + 3*orig + 0] = fxa;
                out[1 + 3*orig + 1] = fya;
                out[1 + 3*orig + 2] = fza;
            }
            en_acc += en;                            // same value in all lanes
        }
        if (lane == 0) g_ewarp[wid] = en_acc;
    }
    grid_bar();

    // ---------------- P5: energy reduction (block 0 only) ------------------
    if (blockIdx.x == 0) {
        float e = 0.f;
        for (int k = tid; k < NWTOT; k += NTHR)      // fixed order: k, k+256, k+512
            e += __ldcg(&g_ewarp[k]);
        s_red[tid] = e;
        __syncthreads();
        for (int off = NTHR / 2; off; off >>= 1) {
            if (tid < off) s_red[tid] += s_red[tid + off];
            __syncthreads();
        }
        if (tid == 0) out[0] = 0.5f * s_red[0];
    }
}

extern "C" void kernel_launch(void* const* d_in, const int* in_sizes, int n_in,
                              void* d_out, int out_size)
{
    const float* pos     = (const float*)d_in[0];
    const float* cell    = (const float*)d_in[1];
    const float* sigm    = (const float*)d_in[2];
    const float* epsm    = (const float*)d_in[3];
    const float* alpm    = (const float*)d_in[4];
    const int*   species = (const int*)  d_in[5];
    const int n = in_sizes[5];
    float* out = (float*)d_out;

    fused_kernel<<<NBLK, NTHR>>>(pos, cell, sigm, epsm, alpm, species, out, n);
}

// round 6
// speedup vs baseline: 1.5063x; 1.5063x over previous
#include <cuda_runtime.h>
#include <math.h>

#define NMAX   8192
#define NCMAX  4096          // max total cells (16^3)
#define NBLK   128
#define NTHR   1024
#define NWTOT  (NBLK * NTHR / 32)   // 4096 warps: one per atom
#define CUTOFF  1.5f
#define CUTOFF2 (CUTOFF * CUTOFF)

// Deterministic scratch (no device-side allocation allowed).
__device__ int      g_cid[NMAX];
__device__ float4   g_pfrac[NMAX];    // wrapped frac coords + species bits
__device__ int      g_count[NCMAX];
__device__ int      g_cursor[NCMAX];
__device__ int      g_slot[NMAX];     // sorted slot -> original atom index
__device__ float4   g_psort[NMAX];    // frac coords + species, cell-sorted
__device__ float    g_ewarp[NWTOT];   // per-warp energy partials
__device__ unsigned g_arrive;         // monotonic barrier ticket counter

// Software grid barrier. Safe: NBLK (128) <= 148 SMs at 1 block/SM => all
// co-resident in wave 1. Monotonic counter stays a multiple of NBLK across
// graph replays, so no reset needed.
__device__ __forceinline__ void grid_bar()
{
    __syncthreads();
    __threadfence();
    if (threadIdx.x == 0) {
        unsigned ticket = atomicAdd(&g_arrive, 1u);
        unsigned target = (ticket / NBLK + 1u) * NBLK;
        while (__ldcg(&g_arrive) < target) { __nanosleep(64); }
    }
    __syncthreads();
}

__global__ __launch_bounds__(NTHR)
void fused_kernel(const float* __restrict__ pos,
                  const float* __restrict__ cell,
                  const float* __restrict__ sigm,
                  const float* __restrict__ epsm,
                  const float* __restrict__ alpm,
                  const int*   __restrict__ species,
                  float* __restrict__ out, int n)
{
    __shared__ float s_inv[9], s_cm[9];
    __shared__ int   s_dims[4];                 // ncx, ncy, ncz, ncell
    __shared__ float s_sig[64], s_eps[64], s_alp[64];
    __shared__ int   s_off[NCMAX + 1];          // per-block copy of cell offsets
    __shared__ int   s_scan[NTHR];
    __shared__ float s_red[NTHR];

    const int tid     = threadIdx.x;
    const int gid     = blockIdx.x * NTHR + tid;
    const int gstride = NBLK * NTHR;

    // ---------------- P0: zero counters, geometry, species tables ----------
    for (int c = gid; c < NCMAX; c += gstride) { g_count[c] = 0; g_cursor[c] = 0; }
    if (tid < 64) {
        s_sig[tid] = sigm[tid];
        s_eps[tid] = epsm[tid];
        s_alp[tid] = alpm[tid];
    }
    if (tid == 0) {
        float c00=cell[0], c01=cell[1], c02=cell[2];
        float c10=cell[3], c11=cell[4], c12=cell[5];
        float c20=cell[6], c21=cell[7], c22=cell[8];
        float cof00 =  (c11*c22 - c12*c21);
        float cof01 = -(c10*c22 - c12*c20);
        float cof02 =  (c10*c21 - c11*c20);
        float cof10 = -(c01*c22 - c02*c21);
        float cof11 =  (c00*c22 - c02*c20);
        float cof12 = -(c00*c21 - c01*c20);
        float cof20 =  (c01*c12 - c02*c11);
        float cof21 = -(c00*c12 - c02*c10);
        float cof22 =  (c00*c11 - c01*c10);
        float det = c00*cof00 + c01*cof01 + c02*cof02;
        float id  = 1.0f / det;
        s_inv[0]=cof00*id; s_inv[1]=cof10*id; s_inv[2]=cof20*id;
        s_inv[3]=cof01*id; s_inv[4]=cof11*id; s_inv[5]=cof21*id;
        s_inv[6]=cof02*id; s_inv[7]=cof12*id; s_inv[8]=cof22*id;
        s_cm[0]=c00; s_cm[1]=c01; s_cm[2]=c02;
        s_cm[3]=c10; s_cm[4]=c11; s_cm[5]=c12;
        s_cm[6]=c20; s_cm[7]=c21; s_cm[8]=c22;
        float lx = sqrtf(c00*c00 + c01*c01 + c02*c02);
        float ly = sqrtf(c10*c10 + c11*c11 + c12*c12);
        float lz = sqrtf(c20*c20 + c21*c21 + c22*c22);
        int ncx = max(1, min(16, (int)floorf(lx / CUTOFF)));
        int ncy = max(1, min(16, (int)floorf(ly / CUTOFF)));
        int ncz = max(1, min(16, (int)floorf(lz / CUTOFF)));
        s_dims[0] = ncx; s_dims[1] = ncy; s_dims[2] = ncz;
        s_dims[3] = ncx * ncy * ncz;
    }
    grid_bar();

    // ---------------- P1: bin atoms into cells -----------------------------
    {
        const int ncx = s_dims[0], ncy = s_dims[1], ncz = s_dims[2];
        for (int i = gid; i < n; i += gstride) {
            float px = pos[3*i], py = pos[3*i+1], pz = pos[3*i+2];
            float fx = px*s_inv[0] + py*s_inv[3] + pz*s_inv[6];
            float fy = px*s_inv[1] + py*s_inv[4] + pz*s_inv[7];
            float fz = px*s_inv[2] + py*s_inv[5] + pz*s_inv[8];
            fx -= floorf(fx); if (fx >= 1.0f) fx = 0.0f;
            fy -= floorf(fy); if (fy >= 1.0f) fy = 0.0f;
            fz -= floorf(fz); if (fz >= 1.0f) fz = 0.0f;
            int cx = min(ncx-1, (int)(fx * (float)ncx));
            int cy = min(ncy-1, (int)(fy * (float)ncy));
            int cz = min(ncz-1, (int)(fz * (float)ncz));
            int cid = (cz * ncy + cy) * ncx + cx;
            g_cid[i]   = cid;
            g_pfrac[i] = make_float4(fx, fy, fz, __int_as_float(species[i]));
            atomicAdd(&g_count[cid], 1);
        }
    }
    grid_bar();

    // ---------------- P2: per-block redundant scan + scatter ---------------
    {
        const int CH = NCMAX / NTHR;          // 4 cells per thread
        int vals[CH];
        int base = tid * CH, sum = 0;
        #pragma unroll
        for (int k = 0; k < CH; k++) { vals[k] = __ldcg(&g_count[base + k]); sum += vals[k]; }
        s_scan[tid] = sum;
        __syncthreads();
        for (int off = 1; off < NTHR; off <<= 1) {
            int add = (tid >= off) ? s_scan[tid - off] : 0;
            __syncthreads();
            s_scan[tid] += add;
            __syncthreads();
        }
        int excl = s_scan[tid] - sum;
        #pragma unroll
        for (int k = 0; k < CH; k++) { s_off[base + k] = excl; excl += vals[k]; }
        if (tid == NTHR - 1) s_off[NCMAX] = s_scan[tid];
        __syncthreads();

        for (int i = gid; i < n; i += gstride) {
            int cid  = g_cid[i];               // same thread wrote it in P1
            int slot = s_off[cid] + atomicAdd(&g_cursor[cid], 1);
            g_slot[slot] = i;
        }
    }
    grid_bar();

    // ---------------- P3: per-cell index sort + gather ---------------------
    {
        const int ncell = s_dims[3];
        for (int c = gid; c < ncell; c += gstride) {
            int s0 = s_off[c], s1 = s_off[c + 1];
            int cnt = s1 - s0;
            if (cnt > 32) cnt = 32;
            int tmp[32];
            for (int k = 0; k < cnt; k++) tmp[k] = __ldcg(&g_slot[s0 + k]);
            for (int a = 1; a < cnt; a++) {          // insertion sort (cells ~3 atoms)
                int key = tmp[a];
                int b = a - 1;
                while (b >= 0 && tmp[b] > key) { tmp[b+1] = tmp[b]; b--; }
                tmp[b+1] = key;
            }
            for (int k = 0; k < cnt; k++) {
                g_slot[s0 + k]  = tmp[k];
                g_psort[s0 + k] = __ldcg(&g_pfrac[tmp[k]]);
            }
        }
    }
    grid_bar();

    // ---------------- P4: pair interactions (one warp per atom) ------------
    {
        const float cm0 = s_cm[0], cm1 = s_cm[1], cm2 = s_cm[2];
        const float cm3 = s_cm[3], cm4 = s_cm[4], cm5 = s_cm[5];
        const float cm6 = s_cm[6], cm7 = s_cm[7], cm8 = s_cm[8];
        const int ncx = s_dims[0], ncy = s_dims[1], ncz = s_dims[2];

        const int wid  = gid >> 5;
        const int lane = tid & 31;

        for (int w = wid; w < n; w += NWTOT) {       // exactly one pass when n==4096
            float4 me = __ldcg(&g_psort[w]);
            int myspec8 = __float_as_int(me.w) * 8;
            int cx = min(ncx-1, (int)(me.x * (float)ncx));
            int cy = min(ncy-1, (int)(me.y * (float)ncy));
            int cz = min(ncz-1, (int)(me.z * (float)ncz));

            int ncid = -1;
            if (lane < 27) {
                int ax = cx + (lane % 3) - 1;
                int ay = cy + ((lane / 3) % 3) - 1;
                int az = cz + (lane / 9) - 1;
                ax += (ax < 0) ? ncx : 0;  ax -= (ax >= ncx) ? ncx : 0;
                ay += (ay < 0) ? ncy : 0;  ay -= (ay >= ncy) ? ncy : 0;
                az += (az < 0) ? ncz : 0;  az -= (az >= ncz) ? ncz : 0;
                ncid = (az * ncy + ay) * ncx + ax;
            }
            unsigned grp = __match_any_sync(0xFFFFFFFFu, ncid);
            bool keep = (lane < 27) && ((__ffs(grp) - 1) == lane);

            int start = 0, end = 0;
            if (keep) { start = s_off[ncid]; end = s_off[ncid + 1]; }

            float fxa = 0.f, fya = 0.f, fza = 0.f, en = 0.f;
            for (int t = start; t < end; t++) {
                if (t == w) continue;                 // self
                float4 o = __ldcg(&g_psort[t]);
                float d0 = o.x - me.x; d0 -= rintf(d0);
                float d1 = o.y - me.y; d1 -= rintf(d1);
                float d2 = o.z - me.z; d2 -= rintf(d2);
                float dx = d0*cm0 + d1*cm3 + d2*cm6;
                float dy = d0*cm1 + d1*cm4 + d2*cm7;
                float dz = d0*cm2 + d1*cm5 + d2*cm8;
                float r2 = dx*dx + dy*dy + dz*dz;
                if (r2 < CUTOFF2) {
                    float r   = sqrtf(r2);
                    int   idx = myspec8 + __float_as_int(o.w);
                    float sg  = s_sig[idx];
                    float fc  = 1.0f - r / sg;
                    if (fc > 0.0f) {
                        float ep  = s_eps[idx];
                        float al  = s_alp[idx];
                        float fa1 = powf(fc, al - 1.0f);     // f^(alpha-1)
                        en += (ep / al) * fa1 * fc;          // (eps/alpha) f^alpha
                        float coef = -(ep / sg) * fa1 / r;   // e'(r)/r
                        fxa += coef * dx;
                        fya += coef * dy;
                        fza += coef * dz;
                    }
                }
            }

            __syncwarp();
            #pragma unroll
            for (int off = 16; off; off >>= 1) {     // deterministic fixed-order tree
                fxa += __shfl_xor_sync(0xFFFFFFFFu, fxa, off);
                fya += __shfl_xor_sync(0xFFFFFFFFu, fya, off);
                fza += __shfl_xor_sync(0xFFFFFFFFu, fza, off);
                en  += __shfl_xor_sync(0xFFFFFFFFu, en,  off);
            }
            if (lane == 0) {
                int orig = __ldcg(&g_slot[w]);
                out[1 + 3*orig + 0] = fxa;
                out[1 + 3*orig + 1] = fya;
                out[1 + 3*orig + 2] = fza;
                g_ewarp[w] = en;
            }
        }
        // zero any unused warp slots (n < NWTOT case handled by exact mapping)
        for (int w = wid + n; w < NWTOT; w += NWTOT) { /* no-op placeholder */ }
    }
    grid_bar();

    // ---------------- P5: energy reduction (block 0 only) ------------------
    if (blockIdx.x == 0) {
        float e = 0.f;
        for (int k = tid; k < n; k += NTHR)          // fixed order: k, k+1024, ...
            e += __ldcg(&g_ewarp[k]);
        s_red[tid] = e;
        __syncthreads();
        for (int off = NTHR / 2; off; off >>= 1) {
            if (tid < off) s_red[tid] += s_red[tid + off];
            __syncthreads();
        }
        if (tid == 0) out[0] = 0.5f * s_red[0];
    }
}

extern "C" void kernel_launch(void* const* d_in, const int* in_sizes, int n_in,
                              void* d_out, int out_size)
{
    const float* pos     = (const float*)d_in[0];
    const float* cell    = (const float*)d_in[1];
    const float* sigm    = (const float*)d_in[2];
    const float* epsm    = (const float*)d_in[3];
    const float* alpm    = (const float*)d_in[4];
    const int*   species = (const int*)  d_in[5];
    const int n = in_sizes[5];
    float* out = (float*)d_out;

    fused_kernel<<<NBLK, NTHR>>>(pos, cell, sigm, epsm, alpm, species, out, n);
}

// round 7
// speedup vs baseline: 1.6433x; 1.0909x over previous
#include <cuda_runtime.h>
#include <math.h>

#define NMAX   8192
#define NCMAX  4096          // max total cells (16^3)
#define NBLK   128
#define NTHR   1024
#define NWTOT  (NBLK * NTHR / 32)   // 4096 warps: one per atom
#define CUTOFF  1.5f
#define CUTOFF2 (CUTOFF * CUTOFF)

// Deterministic scratch (no device-side allocation allowed).
__device__ int      g_cid[NMAX];
__device__ float4   g_pfrac[NMAX];    // wrapped frac coords + species bits
__device__ int      g_count[NCMAX];
__device__ int      g_cursor[NCMAX];
__device__ int      g_slot[NMAX];     // sorted slot -> original atom index
__device__ float4   g_psort[NMAX];    // frac coords + species, cell-sorted
__device__ float    g_ewarp[NWTOT];   // per-warp energy partials
__device__ unsigned g_arrive;         // monotonic barrier ticket counter

// Software grid barrier. Safe: NBLK (128) <= 148 SMs at 1 block/SM => all
// co-resident in wave 1. Monotonic counter stays a multiple of NBLK across
// graph replays, so no reset needed.
// Memory-model note: bar.sync is morally strong, so one release-atomic by
// thread 0 after __syncthreads orders ALL the block's prior writes; the
// acquire-load on the poll side completes the happens-before chain. All
// cross-block global data is additionally read via __ldcg (L2), never L1.
__device__ __forceinline__ void grid_bar()
{
    __syncthreads();
    if (threadIdx.x == 0) {
        unsigned ticket;
        asm volatile("atom.release.gpu.global.add.u32 %0, [%1], %2;"
                     : "=r"(ticket) : "l"(&g_arrive), "r"(1u) : "memory");
        unsigned target = (ticket / NBLK + 1u) * NBLK;
        unsigned cur;
        do {
            asm volatile("ld.acquire.gpu.global.u32 %0, [%1];"
                         : "=r"(cur) : "l"(&g_arrive) : "memory");
            if (cur >= target) break;
            __nanosleep(32);
        } while (true);
    }
    __syncthreads();
}

__global__ __launch_bounds__(NTHR)
void fused_kernel(const float* __restrict__ pos,
                  const float* __restrict__ cell,
                  const float* __restrict__ sigm,
                  const float* __restrict__ epsm,
                  const float* __restrict__ alpm,
                  const int*   __restrict__ species,
                  float* __restrict__ out, int n)
{
    __shared__ float s_inv[9], s_cm[9];
    __shared__ int   s_dims[4];                 // ncx, ncy, ncz, ncell
    __shared__ float s_sig[64], s_eps[64], s_alp[64];
    __shared__ int   s_off[NCMAX + 1];          // per-block copy of cell offsets
    __shared__ int   s_wsum[32];
    __shared__ float s_red[NTHR];

    const int tid     = threadIdx.x;
    const int gid     = blockIdx.x * NTHR + tid;
    const int gstride = NBLK * NTHR;
    const int lane    = tid & 31;
    const int warp    = tid >> 5;

    // ---------------- P0: zero counters, geometry, species tables ----------
    for (int c = gid; c < NCMAX; c += gstride) { g_count[c] = 0; g_cursor[c] = 0; }
    if (tid < 64) {
        s_sig[tid] = sigm[tid];
        s_eps[tid] = epsm[tid];
        s_alp[tid] = alpm[tid];
    }
    if (tid == 0) {
        float c00=cell[0], c01=cell[1], c02=cell[2];
        float c10=cell[3], c11=cell[4], c12=cell[5];
        float c20=cell[6], c21=cell[7], c22=cell[8];
        float cof00 =  (c11*c22 - c12*c21);
        float cof01 = -(c10*c22 - c12*c20);
        float cof02 =  (c10*c21 - c11*c20);
        float cof10 = -(c01*c22 - c02*c21);
        float cof11 =  (c00*c22 - c02*c20);
        float cof12 = -(c00*c21 - c01*c20);
        float cof20 =  (c01*c12 - c02*c11);
        float cof21 = -(c00*c12 - c02*c10);
        float cof22 =  (c00*c11 - c01*c10);
        float det = c00*cof00 + c01*cof01 + c02*cof02;
        float id  = 1.0f / det;
        s_inv[0]=cof00*id; s_inv[1]=cof10*id; s_inv[2]=cof20*id;
        s_inv[3]=cof01*id; s_inv[4]=cof11*id; s_inv[5]=cof21*id;
        s_inv[6]=cof02*id; s_inv[7]=cof12*id; s_inv[8]=cof22*id;
        s_cm[0]=c00; s_cm[1]=c01; s_cm[2]=c02;
        s_cm[3]=c10; s_cm[4]=c11; s_cm[5]=c12;
        s_cm[6]=c20; s_cm[7]=c21; s_cm[8]=c22;
        float lx = sqrtf(c00*c00 + c01*c01 + c02*c02);
        float ly = sqrtf(c10*c10 + c11*c11 + c12*c12);
        float lz = sqrtf(c20*c20 + c21*c21 + c22*c22);
        int ncx = max(1, min(16, (int)floorf(lx / CUTOFF)));
        int ncy = max(1, min(16, (int)floorf(ly / CUTOFF)));
        int ncz = max(1, min(16, (int)floorf(lz / CUTOFF)));
        s_dims[0] = ncx; s_dims[1] = ncy; s_dims[2] = ncz;
        s_dims[3] = ncx * ncy * ncz;
    }
    grid_bar();

    // ---------------- P1: bin atoms into cells -----------------------------
    {
        const int ncx = s_dims[0], ncy = s_dims[1], ncz = s_dims[2];
        for (int i = gid; i < n; i += gstride) {
            float px = pos[3*i], py = pos[3*i+1], pz = pos[3*i+2];
            float fx = px*s_inv[0] + py*s_inv[3] + pz*s_inv[6];
            float fy = px*s_inv[1] + py*s_inv[4] + pz*s_inv[7];
            float fz = px*s_inv[2] + py*s_inv[5] + pz*s_inv[8];
            fx -= floorf(fx); if (fx >= 1.0f) fx = 0.0f;
            fy -= floorf(fy); if (fy >= 1.0f) fy = 0.0f;
            fz -= floorf(fz); if (fz >= 1.0f) fz = 0.0f;
            int cx = min(ncx-1, (int)(fx * (float)ncx));
            int cy = min(ncy-1, (int)(fy * (float)ncy));
            int cz = min(ncz-1, (int)(fz * (float)ncz));
            int cid = (cz * ncy + cy) * ncx + cx;
            g_cid[i]   = cid;
            g_pfrac[i] = make_float4(fx, fy, fz, __int_as_float(species[i]));
            atomicAdd(&g_count[cid], 1);
        }
    }
    grid_bar();

    // ------------ P2: per-block shuffle scan + scatter ----------------------
    {
        const int CH = NCMAX / NTHR;          // 4 cells per thread
        int vals[CH];
        int base = tid * CH, sum = 0;
        #pragma unroll
        for (int k = 0; k < CH; k++) { vals[k] = __ldcg(&g_count[base + k]); sum += vals[k]; }

        int incl = sum;                        // warp-inclusive scan
        #pragma unroll
        for (int off = 1; off < 32; off <<= 1) {
            int v = __shfl_up_sync(0xFFFFFFFFu, incl, off);
            if (lane >= off) incl += v;
        }
        if (lane == 31) s_wsum[warp] = incl;
        __syncthreads();
        if (warp == 0) {                       // scan the 32 warp sums
            int v = s_wsum[lane];
            int w = v;
            #pragma unroll
            for (int off = 1; off < 32; off <<= 1) {
                int u = __shfl_up_sync(0xFFFFFFFFu, w, off);
                if (lane >= off) w += u;
            }
            s_wsum[lane] = w - v;              // exclusive warp offset
        }
        __syncthreads();
        int excl = s_wsum[warp] + incl - sum;
        #pragma unroll
        for (int k = 0; k < CH; k++) { s_off[base + k] = excl; excl += vals[k]; }
        if (tid == NTHR - 1) s_off[NCMAX] = excl;
        __syncthreads();

        for (int i = gid; i < n; i += gstride) {
            int cid  = g_cid[i];               // same thread wrote it in P1
            int slot = s_off[cid] + atomicAdd(&g_cursor[cid], 1);
            g_slot[slot] = i;
        }
    }
    grid_bar();

    // ---------------- P3: per-cell index sort + gather ---------------------
    {
        const int ncell = s_dims[3];
        for (int c = gid; c < ncell; c += gstride) {
            int s0 = s_off[c], s1 = s_off[c + 1];
            int cnt = s1 - s0;
            if (cnt > 32) cnt = 32;
            int tmp[32];
            for (int k = 0; k < cnt; k++) tmp[k] = __ldcg(&g_slot[s0 + k]);
            for (int a = 1; a < cnt; a++) {          // insertion sort (cells ~3 atoms)
                int key = tmp[a];
                int b = a - 1;
                while (b >= 0 && tmp[b] > key) { tmp[b+1] = tmp[b]; b--; }
                tmp[b+1] = key;
            }
            for (int k = 0; k < cnt; k++) {
                g_slot[s0 + k]  = tmp[k];
                g_psort[s0 + k] = __ldcg(&g_pfrac[tmp[k]]);
            }
        }
    }
    grid_bar();

    // ---------------- P4: pair interactions (one warp per atom) ------------
    {
        const float cm0 = s_cm[0], cm1 = s_cm[1], cm2 = s_cm[2];
        const float cm3 = s_cm[3], cm4 = s_cm[4], cm5 = s_cm[5];
        const float cm6 = s_cm[6], cm7 = s_cm[7], cm8 = s_cm[8];
        const int ncx = s_dims[0], ncy = s_dims[1], ncz = s_dims[2];
        const int wid = gid >> 5;

        for (int w = wid; w < n; w += NWTOT) {       // exactly one pass when n==4096
            float4 me = __ldcg(&g_psort[w]);
            int myspec8 = __float_as_int(me.w) * 8;
            int cx = min(ncx-1, (int)(me.x * (float)ncx));
            int cy = min(ncy-1, (int)(me.y * (float)ncy));
            int cz = min(ncz-1, (int)(me.z * (float)ncz));

            int ncid = -1;
            if (lane < 27) {
                int ax = cx + (lane % 3) - 1;
                int ay = cy + ((lane / 3) % 3) - 1;
                int az = cz + (lane / 9) - 1;
                ax += (ax < 0) ? ncx : 0;  ax -= (ax >= ncx) ? ncx : 0;
                ay += (ay < 0) ? ncy : 0;  ay -= (ay >= ncy) ? ncy : 0;
                az += (az < 0) ? ncz : 0;  az -= (az >= ncz) ? ncz : 0;
                ncid = (az * ncy + ay) * ncx + ax;
            }
            unsigned grp = __match_any_sync(0xFFFFFFFFu, ncid);
            bool keep = (lane < 27) && ((__ffs(grp) - 1) == lane);

            int start = 0, end = 0;
            if (keep) { start = s_off[ncid]; end = s_off[ncid + 1]; }

            float fxa = 0.f, fya = 0.f, fza = 0.f, en = 0.f;
            for (int t = start; t < end; t++) {
                if (t == w) continue;                 // self
                float4 o = __ldcg(&g_psort[t]);
                float d0 = o.x - me.x; d0 -= rintf(d0);
                float d1 = o.y - me.y; d1 -= rintf(d1);
                float d2 = o.z - me.z; d2 -= rintf(d2);
                float dx = d0*cm0 + d1*cm3 + d2*cm6;
                float dy = d0*cm1 + d1*cm4 + d2*cm7;
                float dz = d0*cm2 + d1*cm5 + d2*cm8;
                float r2 = dx*dx + dy*dy + dz*dz;
                if (r2 < CUTOFF2) {
                    float r   = sqrtf(r2);
                    int   idx = myspec8 + __float_as_int(o.w);
                    float sg  = s_sig[idx];
                    float fc  = 1.0f - r / sg;
                    if (fc > 0.0f) {
                        float ep  = s_eps[idx];
                        float al  = s_alp[idx];
                        float fa1 = __powf(fc, al - 1.0f);   // fast f^(alpha-1), fc in (0,1]
                        en += (ep / al) * fa1 * fc;          // (eps/alpha) f^alpha
                        float coef = -(ep / sg) * fa1 / r;   // e'(r)/r
                        fxa += coef * dx;
                        fya += coef * dy;
                        fza += coef * dz;
                    }
                }
            }

            __syncwarp();
            #pragma unroll
            for (int off = 16; off; off >>= 1) {     // deterministic fixed-order tree
                fxa += __shfl_xor_sync(0xFFFFFFFFu, fxa, off);
                fya += __shfl_xor_sync(0xFFFFFFFFu, fya, off);
                fza += __shfl_xor_sync(0xFFFFFFFFu, fza, off);
                en  += __shfl_xor_sync(0xFFFFFFFFu, en,  off);
            }
            if (lane == 0) {
                int orig = __ldcg(&g_slot[w]);
                out[1 + 3*orig + 0] = fxa;
                out[1 + 3*orig + 1] = fya;
                out[1 + 3*orig + 2] = fza;
                g_ewarp[w] = en;
            }
        }
    }
    grid_bar();

    // ---------------- P5: energy reduction (block 0 only) ------------------
    if (blockIdx.x == 0) {
        float e = 0.f;
        for (int k = tid; k < n; k += NTHR)          // fixed order: k, k+1024, ...
            e += __ldcg(&g_ewarp[k]);
        s_red[tid] = e;
        __syncthreads();
        for (int off = NTHR / 2; off; off >>= 1) {
            if (tid < off) s_red[tid] += s_red[tid + off];
            __syncthreads();
        }
        if (tid == 0) out[0] = 0.5f * s_red[0];
    }
}

extern "C" void kernel_launch(void* const* d_in, const int* in_sizes, int n_in,
                              void* d_out, int out_size)
{
    const float* pos     = (const float*)d_in[0];
    const float* cell    = (const float*)d_in[1];
    const float* sigm    = (const float*)d_in[2];
    const float* epsm    = (const float*)d_in[3];
    const float* alpm    = (const float*)d_in[4];
    const int*   species = (const int*)  d_in[5];
    const int n = in_sizes[5];
    float* out = (float*)d_out;

    fused_kernel<<<NBLK, NTHR>>>(pos, cell, sigm, epsm, alpm, species, out, n);
}